// round 5
// baseline (speedup 1.0000x reference)
#include <cuda_runtime.h>
#include <cuda_fp16.h>

#define NU 100000
#define MI 50000
#define NN (NU + MI)
#define D 64
#define ND (NN * D)
#define ND4 (ND / 4)
#define MAXE 2000000

// Static scratch (no dynamic allocation allowed).
static __device__ __half g_h0[ND];                    // fp16 copy of concat(eu0, ei0)
static __device__ __half g_a[ND];                     // layer 1 out (fp16)
static __device__ __half g_b[ND];                     // layer 2 out (fp16)
static __device__ __half g_c[ND];                     // layer 3 out (fp16)
static __device__ unsigned long long g_edges[MAXE];   // packed {val:f32, col:int32}
static __device__ int g_rowptr[NN + 1];
static __device__ int g_cursor[MI];                   // item histogram, then cursors

// ---------------------------------------------------------------------------
// convert inputs to fp16 table; clear item histogram; out[2B] = 0
__global__ void convert_init_kernel(const float4* __restrict__ eu,
                                    const float4* __restrict__ ei,
                                    float* __restrict__ out, int B) {
    int i = blockIdx.x * blockDim.x + threadIdx.x;
    if (i < ND4) {
        const int NU4 = NU * D / 4;
        float4 v = (i < NU4) ? __ldg(eu + i) : __ldg(ei + (i - NU4));
        half2 h[2];
        h[0] = __floats2half2_rn(v.x, v.y);
        h[1] = __floats2half2_rn(v.z, v.w);
        ((uint2*)g_h0)[i] = *(uint2*)h;
    }
    if (i < MI) g_cursor[i] = 0;
    if (i == 0) out[2 * B] = 0.f;
}

// fused: user rowptr by boundary detection (first half, sorted) +
//        item-degree histogram (second half). 4 edges per thread for ILP.
__global__ void hist_bound_kernel(const int* __restrict__ rows, int H) {
    int e0 = (blockIdx.x * blockDim.x + threadIdx.x) * 4;
    if (e0 >= H) return;
    int prev = (e0 == 0) ? -1 : __ldg(&rows[e0 - 1]);
#pragma unroll
    for (int k = 0; k < 4; k++) {
        int e = e0 + k;
        if (e < H) {
            int cur = __ldg(&rows[e]);
            for (int r = prev + 1; r <= cur; r++) g_rowptr[r] = e;
            if (e == H - 1)
                for (int r = cur + 1; r <= NU; r++) g_rowptr[r] = H;
            prev = cur;
        }
    }
#pragma unroll
    for (int k = 0; k < 4; k++) {
        int e = e0 + k;
        if (e < H) atomicAdd(&g_cursor[__ldg(&rows[H + e]) - NU], 1);
    }
}

// single-block exclusive scan of the 50k item degrees -> item rowptr + cursors
__global__ void scan_kernel(int H, int E) {
    __shared__ int sh[1024];
    const int PER = (MI + 1023) / 1024;   // 49
    int t = threadIdx.x;
    int base = t * PER;
    int s = 0;
    for (int k = 0; k < PER; k++) {
        int idx = base + k;
        if (idx < MI) s += g_cursor[idx];
    }
    sh[t] = s;
    __syncthreads();
    for (int off = 1; off < 1024; off <<= 1) {
        int y = (t >= off) ? sh[t - off] : 0;
        __syncthreads();
        sh[t] += y;
        __syncthreads();
    }
    int run = sh[t] - s + H;   // exclusive prefix + user-half base
    for (int k = 0; k < PER; k++) {
        int idx = base + k;
        if (idx < MI) {
            int c = g_cursor[idx];
            g_rowptr[NU + idx] = run;
            g_cursor[idx] = run;
            run += c;
        }
    }
    if (t == 0) g_rowptr[NN] = E;
}

// build CSR edge array: first half identity copy (already row-sorted),
// second half atomic scatter into item rows. 4 edges per thread for ILP.
__global__ void build_edges_kernel(const int* __restrict__ rows,
                                   const int* __restrict__ cols,
                                   const float* __restrict__ vals, int H) {
    int e0 = (blockIdx.x * blockDim.x + threadIdx.x) * 4;
    int E2 = 2 * H;
    if (e0 >= E2) return;
    int pos[4];
#pragma unroll
    for (int k = 0; k < 4; k++) {
        int e = e0 + k;
        if (e < H) pos[k] = e;
        else if (e < E2) pos[k] = atomicAdd(&g_cursor[__ldg(&rows[e]) - NU], 1);
    }
#pragma unroll
    for (int k = 0; k < 4; k++) {
        int e = e0 + k;
        if (e < E2) {
            unsigned long long pk =
                ((unsigned long long)__float_as_uint(__ldg(&vals[e])) << 32) |
                (unsigned int)__ldg(&cols[e]);
            g_edges[pos[k]] = pk;
        }
    }
}

// ---------------------------------------------------------------------------
// CSR gather SpMM (fp16 storage, fp32 accumulation).
// ONE WARP PER ROW: 32 lanes x 2 halves = 64 dims. One edge per iteration for
// the whole warp -> fully coalesced 128B gathers (1 wavefront), no divergence,
// no cross-lane reduction. Unrolled x4 for MLP.
__global__ void spmm_kernel(const __half* __restrict__ src,
                            __half* __restrict__ dst) {
    int w = (int)((blockIdx.x * (long long)blockDim.x + threadIdx.x) >> 5);
    int lane = threadIdx.x & 31;
    if (w >= NN) return;
    int beg = g_rowptr[w];
    int end = g_rowptr[w + 1];
    const unsigned* sp = (const unsigned*)src;   // 32 x u32 (half2) per row

    float sx = 0.f, sy = 0.f;

    int j = beg;
    for (; j + 4 <= end; j += 4) {
        unsigned long long pk0 = __ldg(&g_edges[j]);
        unsigned long long pk1 = __ldg(&g_edges[j + 1]);
        unsigned long long pk2 = __ldg(&g_edges[j + 2]);
        unsigned long long pk3 = __ldg(&g_edges[j + 3]);
        unsigned x0 = __ldg(sp + (int)(unsigned int)pk0 * 32 + lane);
        unsigned x1 = __ldg(sp + (int)(unsigned int)pk1 * 32 + lane);
        unsigned x2 = __ldg(sp + (int)(unsigned int)pk2 * 32 + lane);
        unsigned x3 = __ldg(sp + (int)(unsigned int)pk3 * 32 + lane);
        float v0 = __uint_as_float((unsigned int)(pk0 >> 32));
        float v1 = __uint_as_float((unsigned int)(pk1 >> 32));
        float v2 = __uint_as_float((unsigned int)(pk2 >> 32));
        float v3 = __uint_as_float((unsigned int)(pk3 >> 32));
        float2 f0 = __half22float2(*(half2*)&x0);
        float2 f1 = __half22float2(*(half2*)&x1);
        float2 f2 = __half22float2(*(half2*)&x2);
        float2 f3 = __half22float2(*(half2*)&x3);
        sx += v0 * f0.x; sy += v0 * f0.y;
        sx += v1 * f1.x; sy += v1 * f1.y;
        sx += v2 * f2.x; sy += v2 * f2.y;
        sx += v3 * f3.x; sy += v3 * f3.y;
    }
    for (; j < end; j++) {
        unsigned long long pk = __ldg(&g_edges[j]);
        unsigned x = __ldg(sp + (int)(unsigned int)pk * 32 + lane);
        float v = __uint_as_float((unsigned int)(pk >> 32));
        float2 f = __half22float2(*(half2*)&x);
        sx += v * f.x; sy += v * f.y;
    }

    half2 o = __floats2half2_rn(sx, sy);
    ((unsigned*)dst)[w * 32 + lane] = *(unsigned*)&o;
}

// ---------------------------------------------------------------------------
// One warp per batch element; sums e0 (fp32) + 3 layer terms (fp16).
__global__ void final_kernel(const float* __restrict__ eu0,
                             const float* __restrict__ ei0,
                             const int* __restrict__ user,
                             const int* __restrict__ item_i,
                             const int* __restrict__ item_j,
                             float* __restrict__ out, int B) {
    int w = (int)((blockIdx.x * (long long)blockDim.x + threadIdx.x) >> 5);
    int lane = threadIdx.x & 31;
    if (w >= B) return;
    int u = user[w];
    int a = item_i[w];
    int b = item_j[w];
    int ou = u * 32 + lane;                // half2 index (D/2 = 32 per row)
    int oi = (NU + a) * 32 + lane;
    int oj = (NU + b) * 32 + lane;

    float2 u0 = ((const float2*)eu0)[u * 32 + lane];
    float2 i0 = ((const float2*)ei0)[a * 32 + lane];
    float2 j0 = ((const float2*)ei0)[b * 32 + lane];

    float2 au = u0, ai = i0, aj = j0;
    float2 t;
#define ADD(dst, arr, idx) { t = __half22float2(((const half2*)arr)[idx]); \
                             dst.x += t.x; dst.y += t.y; }
    ADD(au, g_a, ou) ADD(au, g_b, ou) ADD(au, g_c, ou)
    ADD(ai, g_a, oi) ADD(ai, g_b, oi) ADD(ai, g_c, oi)
    ADD(aj, g_a, oj) ADD(aj, g_b, oj) ADD(aj, g_c, oj)
#undef ADD

    float pi = au.x * ai.x + au.y * ai.y;
    float pj = au.x * aj.x + au.y * aj.y;
    float reg = u0.x * u0.x + u0.y * u0.y + i0.x * i0.x + i0.y * i0.y
              + j0.x * j0.x + j0.y * j0.y;

#pragma unroll
    for (int o = 16; o; o >>= 1) {
        pi  += __shfl_xor_sync(0xFFFFFFFFu, pi, o);
        pj  += __shfl_xor_sync(0xFFFFFFFFu, pj, o);
        reg += __shfl_xor_sync(0xFFFFFFFFu, reg, o);
    }
    if (lane == 0) {
        out[w]     = pi * (1.f / 16.f);   // (1/4)^2 from the /(N_LAYERS+1) mean
        out[B + w] = pj * (1.f / 16.f);
        atomicAdd(out + 2 * B, reg * (0.5f / (float)B));
    }
}

// ---------------------------------------------------------------------------
extern "C" void kernel_launch(void* const* d_in, const int* in_sizes, int n_in,
                              void* d_out, int out_size) {
    const float* eu0    = (const float*)d_in[0];
    const float* ei0    = (const float*)d_in[1];
    const int*   rows   = (const int*)d_in[2];
    const int*   cols   = (const int*)d_in[3];
    const float* vals   = (const float*)d_in[4];
    const int*   user   = (const int*)d_in[5];
    const int*   item_i = (const int*)d_in[6];
    const int*   item_j = (const int*)d_in[7];

    int E = in_sizes[2];
    int H = E / 2;          // first half: user rows (sorted); second: item rows
    int B = in_sizes[5];
    float* out = (float*)d_out;

    __half *ph0, *pa, *pb, *pc;
    cudaGetSymbolAddress((void**)&ph0, g_h0);
    cudaGetSymbolAddress((void**)&pa, g_a);
    cudaGetSymbolAddress((void**)&pb, g_b);
    cudaGetSymbolAddress((void**)&pc, g_c);

    const int T = 256;

    convert_init_kernel<<<(ND4 + T - 1) / T, T>>>((const float4*)eu0,
                                                  (const float4*)ei0, out, B);
    hist_bound_kernel<<<(H + T * 4 - 1) / (T * 4), T>>>(rows, H);
    scan_kernel<<<1, 1024>>>(H, E);
    build_edges_kernel<<<(E + T * 4 - 1) / (T * 4), T>>>(rows, cols, vals, H);

    int sgrid = (NN * 32 + T - 1) / T;
    spmm_kernel<<<sgrid, T>>>(ph0, pa);   // layer 1
    spmm_kernel<<<sgrid, T>>>(pa, pb);    // layer 2
    spmm_kernel<<<sgrid, T>>>(pb, pc);    // layer 3

    final_kernel<<<(B * 32 + T - 1) / T, T>>>(eu0, ei0, user, item_i, item_j, out, B);
}

// round 6
// speedup vs baseline: 1.3389x; 1.3389x over previous
#include <cuda_runtime.h>
#include <cuda_fp16.h>

#define NU 100000
#define MI 50000
#define NN (NU + MI)
#define D 64
#define ND (NN * D)
#define ND4 (ND / 4)
#define MAXE 2000000

// Static scratch (no dynamic allocation allowed).
static __device__ __half g_h0[ND];                    // fp16 copy of concat(eu0, ei0)
static __device__ __half g_a[ND];                     // layer 1 out (fp16)
static __device__ __half g_b[ND];                     // layer 2 out (fp16)
static __device__ unsigned long long g_edges[MAXE];   // packed {val:f32, col:int32}
static __device__ int g_rowptr[NN + 1];
static __device__ int g_cursor[MI];                   // item histogram, then cursors

// ---------------------------------------------------------------------------
// convert inputs to fp16 table; clear item histogram; out[2B] = 0
__global__ void convert_init_kernel(const float4* __restrict__ eu,
                                    const float4* __restrict__ ei,
                                    float* __restrict__ out, int B) {
    int i = blockIdx.x * blockDim.x + threadIdx.x;
    if (i < ND4) {
        const int NU4 = NU * D / 4;
        float4 v = (i < NU4) ? __ldg(eu + i) : __ldg(ei + (i - NU4));
        half2 h[2];
        h[0] = __floats2half2_rn(v.x, v.y);
        h[1] = __floats2half2_rn(v.z, v.w);
        ((uint2*)g_h0)[i] = *(uint2*)h;
    }
    if (i < MI) g_cursor[i] = 0;
    if (i == 0) out[2 * B] = 0.f;
}

// fused: user rowptr by boundary detection (first half, sorted) +
//        item-degree histogram (second half). 1 edge per thread.
__global__ void hist_bound_kernel(const int* __restrict__ rows, int H) {
    int e = blockIdx.x * blockDim.x + threadIdx.x;
    if (e >= H) return;
    int cur = __ldg(&rows[e]);
    int prev = (e == 0) ? -1 : __ldg(&rows[e - 1]);
    for (int r = prev + 1; r <= cur; r++) g_rowptr[r] = e;
    if (e == H - 1)
        for (int r = cur + 1; r <= NU; r++) g_rowptr[r] = H;
    atomicAdd(&g_cursor[__ldg(&rows[H + e]) - NU], 1);
}

// single-block exclusive scan of the 50k item degrees -> item rowptr + cursors
__global__ void scan_kernel(int H, int E) {
    __shared__ int sh[1024];
    const int PER = (MI + 1023) / 1024;   // 49
    int t = threadIdx.x;
    int base = t * PER;
    int s = 0;
    for (int k = 0; k < PER; k++) {
        int idx = base + k;
        if (idx < MI) s += g_cursor[idx];
    }
    sh[t] = s;
    __syncthreads();
    for (int off = 1; off < 1024; off <<= 1) {
        int y = (t >= off) ? sh[t - off] : 0;
        __syncthreads();
        sh[t] += y;
        __syncthreads();
    }
    int run = sh[t] - s + H;   // exclusive prefix + user-half base
    for (int k = 0; k < PER; k++) {
        int idx = base + k;
        if (idx < MI) {
            int c = g_cursor[idx];
            g_rowptr[NU + idx] = run;
            g_cursor[idx] = run;
            run += c;
        }
    }
    if (t == 0) g_rowptr[NN] = E;
}

// build CSR edge array: first half identity copy (already row-sorted),
// second half atomic scatter into item rows. 1 edge per thread.
__global__ void build_edges_kernel(const int* __restrict__ rows,
                                   const int* __restrict__ cols,
                                   const float* __restrict__ vals, int H) {
    int e = blockIdx.x * blockDim.x + threadIdx.x;
    if (e < H) {
        unsigned long long pk =
            ((unsigned long long)__float_as_uint(vals[e]) << 32) | (unsigned int)cols[e];
        g_edges[e] = pk;
    } else if (e < 2 * H) {
        int r = rows[e] - NU;
        int pos = atomicAdd(&g_cursor[r], 1);
        unsigned long long pk =
            ((unsigned long long)__float_as_uint(vals[e]) << 32) | (unsigned int)cols[e];
        g_edges[pos] = pk;
    }
}

// ---------------------------------------------------------------------------
// CSR gather SpMM (fp16 storage, fp32 accumulation).
// 8 lanes per row, 16B (8 halves) per lane; edge loop unrolled x4 for MLP.
// (R4 layout — measured fastest.)
__global__ void spmm_kernel(const __half* __restrict__ src,
                            __half* __restrict__ dst) {
    int gid = blockIdx.x * blockDim.x + threadIdx.x;
    int row = gid >> 3;
    int l = gid & 7;
    if (row >= NN) return;
    int beg = g_rowptr[row];
    int end = g_rowptr[row + 1];
    const uint4* sp = (const uint4*)src;   // 8 x uint4 per row

    float s0 = 0.f, s1 = 0.f, s2 = 0.f, s3 = 0.f,
          s4 = 0.f, s5 = 0.f, s6 = 0.f, s7 = 0.f;

#define ACC(PK, X) {                                                     \
        float v = __uint_as_float((unsigned int)((PK) >> 32));           \
        half2* h = (half2*)&(X);                                         \
        float2 f0 = __half22float2(h[0]);                                \
        float2 f1 = __half22float2(h[1]);                                \
        float2 f2 = __half22float2(h[2]);                                \
        float2 f3 = __half22float2(h[3]);                                \
        s0 += v * f0.x; s1 += v * f0.y; s2 += v * f1.x; s3 += v * f1.y;  \
        s4 += v * f2.x; s5 += v * f2.y; s6 += v * f3.x; s7 += v * f3.y; }

    int j = beg;
    for (; j + 4 <= end; j += 4) {
        unsigned long long pk0 = __ldg(&g_edges[j]);
        unsigned long long pk1 = __ldg(&g_edges[j + 1]);
        unsigned long long pk2 = __ldg(&g_edges[j + 2]);
        unsigned long long pk3 = __ldg(&g_edges[j + 3]);
        uint4 x0 = __ldg(sp + (int)(unsigned int)pk0 * 8 + l);
        uint4 x1 = __ldg(sp + (int)(unsigned int)pk1 * 8 + l);
        uint4 x2 = __ldg(sp + (int)(unsigned int)pk2 * 8 + l);
        uint4 x3 = __ldg(sp + (int)(unsigned int)pk3 * 8 + l);
        ACC(pk0, x0) ACC(pk1, x1) ACC(pk2, x2) ACC(pk3, x3)
    }
    for (; j < end; j++) {
        unsigned long long pk = __ldg(&g_edges[j]);
        uint4 x = __ldg(sp + (int)(unsigned int)pk * 8 + l);
        ACC(pk, x)
    }
#undef ACC

    half2 o[4];
    o[0] = __floats2half2_rn(s0, s1);
    o[1] = __floats2half2_rn(s2, s3);
    o[2] = __floats2half2_rn(s4, s5);
    o[3] = __floats2half2_rn(s6, s7);
    ((uint4*)dst)[row * 8 + l] = *(uint4*)o;
}

// ---------------------------------------------------------------------------
// Fused layer-3 + scoring: one warp per batch element.
// For each of its 3 nodes, computes layer3[n] = sum_e v * l2[c] on the fly
// (lane owns 2 dims as half2), adds e0 (fp32) + l1 + l2 (fp16), then dots.
__device__ __forceinline__ void node_acc(int n, int lane,
                                         const float2* __restrict__ e0_2,
                                         long long e0_row,
                                         float& ax, float& ay) {
    // layer 0 (fp32 from inputs)
    float2 v0 = __ldg(e0_2 + e0_row * 32 + lane);
    ax = v0.x; ay = v0.y;
    // layers 1 & 2 (fp16 stored)
    float2 t;
    t = __half22float2(((const half2*)g_a)[n * 32 + lane]); ax += t.x; ay += t.y;
    t = __half22float2(((const half2*)g_b)[n * 32 + lane]); ax += t.x; ay += t.y;
    // layer 3 on the fly from l2 (= g_b)
    int beg = g_rowptr[n];
    int end = g_rowptr[n + 1];
    const unsigned* sp = (const unsigned*)g_b;
    int j = beg;
    for (; j + 4 <= end; j += 4) {
        unsigned long long pk0 = __ldg(&g_edges[j]);
        unsigned long long pk1 = __ldg(&g_edges[j + 1]);
        unsigned long long pk2 = __ldg(&g_edges[j + 2]);
        unsigned long long pk3 = __ldg(&g_edges[j + 3]);
        unsigned x0 = __ldg(sp + (int)(unsigned int)pk0 * 32 + lane);
        unsigned x1 = __ldg(sp + (int)(unsigned int)pk1 * 32 + lane);
        unsigned x2 = __ldg(sp + (int)(unsigned int)pk2 * 32 + lane);
        unsigned x3 = __ldg(sp + (int)(unsigned int)pk3 * 32 + lane);
        float v0f = __uint_as_float((unsigned int)(pk0 >> 32));
        float v1f = __uint_as_float((unsigned int)(pk1 >> 32));
        float v2f = __uint_as_float((unsigned int)(pk2 >> 32));
        float v3f = __uint_as_float((unsigned int)(pk3 >> 32));
        float2 f0 = __half22float2(*(half2*)&x0);
        float2 f1 = __half22float2(*(half2*)&x1);
        float2 f2 = __half22float2(*(half2*)&x2);
        float2 f3 = __half22float2(*(half2*)&x3);
        ax += v0f * f0.x; ay += v0f * f0.y;
        ax += v1f * f1.x; ay += v1f * f1.y;
        ax += v2f * f2.x; ay += v2f * f2.y;
        ax += v3f * f3.x; ay += v3f * f3.y;
    }
    for (; j < end; j++) {
        unsigned long long pk = __ldg(&g_edges[j]);
        unsigned x = __ldg(sp + (int)(unsigned int)pk * 32 + lane);
        float v = __uint_as_float((unsigned int)(pk >> 32));
        float2 f = __half22float2(*(half2*)&x);
        ax += v * f.x; ay += v * f.y;
    }
}

__global__ void final_kernel(const float* __restrict__ eu0,
                             const float* __restrict__ ei0,
                             const int* __restrict__ user,
                             const int* __restrict__ item_i,
                             const int* __restrict__ item_j,
                             float* __restrict__ out, int B) {
    int w = (int)((blockIdx.x * (long long)blockDim.x + threadIdx.x) >> 5);
    int lane = threadIdx.x & 31;
    if (w >= B) return;
    int u = user[w];
    int a = item_i[w];
    int b = item_j[w];

    float ux, uy, ix, iy, jx, jy;
    node_acc(u,      lane, (const float2*)eu0, u, ux, uy);
    node_acc(NU + a, lane, (const float2*)ei0, a, ix, iy);
    node_acc(NU + b, lane, (const float2*)ei0, b, jx, jy);

    float pi = ux * ix + uy * iy;
    float pj = ux * jx + uy * jy;

    float2 u0 = ((const float2*)eu0)[(long long)u * 32 + lane];
    float2 i0 = ((const float2*)ei0)[(long long)a * 32 + lane];
    float2 j0 = ((const float2*)ei0)[(long long)b * 32 + lane];
    float reg = u0.x * u0.x + u0.y * u0.y + i0.x * i0.x + i0.y * i0.y
              + j0.x * j0.x + j0.y * j0.y;

#pragma unroll
    for (int o = 16; o; o >>= 1) {
        pi  += __shfl_xor_sync(0xFFFFFFFFu, pi, o);
        pj  += __shfl_xor_sync(0xFFFFFFFFu, pj, o);
        reg += __shfl_xor_sync(0xFFFFFFFFu, reg, o);
    }
    if (lane == 0) {
        out[w]     = pi * (1.f / 16.f);   // (1/4)^2 from the /(N_LAYERS+1) mean
        out[B + w] = pj * (1.f / 16.f);
        atomicAdd(out + 2 * B, reg * (0.5f / (float)B));
    }
}

// ---------------------------------------------------------------------------
extern "C" void kernel_launch(void* const* d_in, const int* in_sizes, int n_in,
                              void* d_out, int out_size) {
    const float* eu0    = (const float*)d_in[0];
    const float* ei0    = (const float*)d_in[1];
    const int*   rows   = (const int*)d_in[2];
    const int*   cols   = (const int*)d_in[3];
    const float* vals   = (const float*)d_in[4];
    const int*   user   = (const int*)d_in[5];
    const int*   item_i = (const int*)d_in[6];
    const int*   item_j = (const int*)d_in[7];

    int E = in_sizes[2];
    int H = E / 2;          // first half: user rows (sorted); second: item rows
    int B = in_sizes[5];
    float* out = (float*)d_out;

    __half *ph0, *pa, *pb;
    cudaGetSymbolAddress((void**)&ph0, g_h0);
    cudaGetSymbolAddress((void**)&pa, g_a);
    cudaGetSymbolAddress((void**)&pb, g_b);

    const int T = 256;

    convert_init_kernel<<<(ND4 + T - 1) / T, T>>>((const float4*)eu0,
                                                  (const float4*)ei0, out, B);
    hist_bound_kernel<<<(H + T - 1) / T, T>>>(rows, H);
    scan_kernel<<<1, 1024>>>(H, E);
    build_edges_kernel<<<(E + T - 1) / T, T>>>(rows, cols, vals, H);

    int sgrid = (NN * 8 + T - 1) / T;
    spmm_kernel<<<sgrid, T>>>(ph0, pa);   // layer 1
    spmm_kernel<<<sgrid, T>>>(pa, pb);    // layer 2
    // layer 3 fused into final_kernel (only batch rows needed)

    final_kernel<<<(B * 32 + T - 1) / T, T>>>(eu0, ei0, user, item_i, item_j, out, B);
}